// round 13
// baseline (speedup 1.0000x reference)
#include <cuda_runtime.h>
#include <math.h>

#define NV   8192
#define FIN  512
#define FOUT 256

// ------------- scratch (device globals; allocation is forbidden) -------------
__device__ float  g_h[NV * FOUT];   // h = x @ W   (8 MB)
__device__ float4 g_sp[NV];         // {s, e^s, e^{0.2s}, 0}
__device__ float4 g_dp[NV];         // {d, e^d, e^{0.2d}, 0}

// ------------- f32x2 helpers -------------------------------------------------
__device__ __forceinline__ unsigned long long dup2(float v) {
    unsigned long long r;
    asm("mov.b64 %0, {%1, %1};" : "=l"(r) : "f"(v));
    return r;
}
__device__ __forceinline__ unsigned long long fma2(unsigned long long a,
                                                   unsigned long long b,
                                                   unsigned long long c) {
    unsigned long long d;
    asm("fma.rn.f32x2 %0, %1, %2, %3;" : "=l"(d) : "l"(a), "l"(b), "l"(c));
    return d;
}

// ============ kernel 1: h = x @ W  (8192x512 @ 512x256) ======================
// BM=128, BN=64, BK=32, 256 threads, micro-tile 8(M) x 4(N), N-paired f32x2.
__global__ __launch_bounds__(256, 2) void k_gemm_xw(const float* __restrict__ x,
                                                    const float* __restrict__ W) {
    __shared__ float As[32][128];   // [k][m]
    __shared__ float Ws[32][64];    // [k][n]
    const int tid = threadIdx.x;
    const int i0 = blockIdx.y * 128, c0 = blockIdx.x * 64;

    const int bm = tid >> 1, kg = tid & 1;          // A staging: row bm, 16 k's
    const int ty = tid >> 4, tx = tid & 15;
    const int m0 = ty * 8, n0 = tx * 4;

    unsigned long long acc[8][2];
#pragma unroll
    for (int r = 0; r < 8; r++) { acc[r][0] = 0ULL; acc[r][1] = 0ULL; }

    const float* xrow = x + (size_t)(i0 + bm) * FIN + kg * 16;

    for (int t = 0; t < FIN / 32; t++) {
        const int k0 = t * 32;
        // stage A (x): 16 scalars per thread, transposed into [k][m]
#pragma unroll
        for (int e = 0; e < 4; e++) {
            float4 v = *(const float4*)(xrow + k0 + e * 4);
            As[kg * 16 + e * 4 + 0][bm] = v.x;
            As[kg * 16 + e * 4 + 1][bm] = v.y;
            As[kg * 16 + e * 4 + 2][bm] = v.z;
            As[kg * 16 + e * 4 + 3][bm] = v.w;
        }
        // stage W: 2 float4 per thread
#pragma unroll
        for (int q = 0; q < 2; q++) {
            int idx = tid + q * 256;
            int r = idx >> 4, c4 = (idx & 15) * 4;
            *(float4*)&Ws[r][c4] = *(const float4*)(W + (size_t)(k0 + r) * FOUT + c0 + c4);
        }
        __syncthreads();
#pragma unroll
        for (int kk = 0; kk < 32; kk++) {
            float4 a0 = *(const float4*)&As[kk][m0];
            float4 a1 = *(const float4*)&As[kk][m0 + 4];
            ulonglong2 b = *(const ulonglong2*)&Ws[kk][n0];
            unsigned long long ad[8] = {dup2(a0.x), dup2(a0.y), dup2(a0.z), dup2(a0.w),
                                        dup2(a1.x), dup2(a1.y), dup2(a1.z), dup2(a1.w)};
#pragma unroll
            for (int r = 0; r < 8; r++) {
                acc[r][0] = fma2(ad[r], b.x, acc[r][0]);
                acc[r][1] = fma2(ad[r], b.y, acc[r][1]);
            }
        }
        __syncthreads();
    }
#pragma unroll
    for (int r = 0; r < 8; r++) {
        ulonglong2 o; o.x = acc[r][0]; o.y = acc[r][1];
        *(ulonglong2*)&g_h[(size_t)(i0 + m0 + r) * FOUT + c0 + n0] = o;
    }
}

// ============ kernel 2: per-node scores + exponentials =======================
// one warp per node; f_src = h_i . a[0:256], f_dst = h_i . a[256:512]
__global__ void k_scores(const float* __restrict__ a) {
    const int node = blockIdx.x * 8 + (threadIdx.x >> 5);
    const int l = threadIdx.x & 31;
    const float* hr = g_h + (size_t)node * FOUT + l * 8;
    float4 h0 = *(const float4*)hr;
    float4 h1 = *(const float4*)(hr + 4);
    const float* aL = a + l * 8;
    const float* aR = a + FOUT + l * 8;
    float4 l0 = *(const float4*)aL, l1 = *(const float4*)(aL + 4);
    float4 r0 = *(const float4*)aR, r1 = *(const float4*)(aR + 4);
    float s = h0.x * l0.x + h0.y * l0.y + h0.z * l0.z + h0.w * l0.w
            + h1.x * l1.x + h1.y * l1.y + h1.z * l1.z + h1.w * l1.w;
    float d = h0.x * r0.x + h0.y * r0.y + h0.z * r0.z + h0.w * r0.w
            + h1.x * r1.x + h1.y * r1.y + h1.z * r1.z + h1.w * r1.w;
#pragma unroll
    for (int off = 16; off; off >>= 1) {
        s += __shfl_xor_sync(0xFFFFFFFFu, s, off);
        d += __shfl_xor_sync(0xFFFFFFFFu, d, off);
    }
    if (l == 0) {
        g_sp[node] = make_float4(s, expf(s), expf(0.2f * s), 0.f);
        g_dp[node] = make_float4(d, expf(d), expf(0.2f * d), 0.f);
    }
}

// ============ kernel 3: fused masked-softmax attention GEMM ==================
// out = diag(1/denom) * P @ h,  P built on the fly from adj + separable scores.
// BM=64, BN=128, BK=32, 256 threads, micro-tile 8(M) x 4(N), N-paired f32x2.
__global__ __launch_bounds__(256, 2) void k_attn(const int* __restrict__ adj,
                                                 float* __restrict__ out) {
    __shared__ float Ps[32][64];     // [j][m] unnormalized weights
    __shared__ float Hs[32][128];    // [j][n]
    __shared__ float denomS[64];
    const int tid = threadIdx.x;
    const int c0 = blockIdx.x * 128;   // 2 column blocks
    const int i0 = blockIdx.y * 64;    // 128 row blocks

    const int bm = tid >> 2, jg = tid & 3;   // build: row bm, 8 j's per thread
    const int ty = tid >> 5, tx = tid & 31;  // compute
    const int m0 = ty * 8, n0 = tx * 4;
    const int hrow = tid >> 5, hc = (tid & 31) * 4;  // Hs staging

    if (tid < 64) denomS[tid] = 0.f;

    unsigned long long acc[8][2];
#pragma unroll
    for (int r = 0; r < 8; r++) { acc[r][0] = 0ULL; acc[r][1] = 0ULL; }

    float dsum = 0.f;
    const float4 sp = g_sp[i0 + bm];
    const int* arow = adj + (size_t)(i0 + bm) * NV + jg * 8;

    for (int t = 0; t < NV / 32; t++) {
        const int j0 = t * 32;
        // stage Hs: 4 float4 per thread
#pragma unroll
        for (int q = 0; q < 4; q++) {
            int r = hrow + q * 8;
            *(float4*)&Hs[r][hc] = *(const float4*)(g_h + (size_t)(j0 + r) * FOUT + c0 + hc);
        }
        // build Ps: 8 entries per thread (row bm, j = jg*8 .. jg*8+7)
#pragma unroll
        for (int e4 = 0; e4 < 2; e4++) {
            int4 av = *(const int4*)(arow + j0 + e4 * 4);
            int aa[4] = {av.x, av.y, av.z, av.w};
#pragma unroll
            for (int u = 0; u < 4; u++) {
                int jloc = jg * 8 + e4 * 4 + u;
                float4 dp = g_dp[j0 + jloc];
                float z = sp.x + dp.x;
                float v = (z > 0.f) ? (sp.y * dp.y) : (sp.z * dp.z);
                v = (aa[u] > 0) ? v : 0.f;
                Ps[jloc][bm] = v;
                dsum += v;
            }
        }
        __syncthreads();
#pragma unroll
        for (int kk = 0; kk < 32; kk++) {
            float4 a0 = *(const float4*)&Ps[kk][m0];
            float4 a1 = *(const float4*)&Ps[kk][m0 + 4];
            ulonglong2 b = *(const ulonglong2*)&Hs[kk][n0];
            unsigned long long ad[8] = {dup2(a0.x), dup2(a0.y), dup2(a0.z), dup2(a0.w),
                                        dup2(a1.x), dup2(a1.y), dup2(a1.z), dup2(a1.w)};
#pragma unroll
            for (int r = 0; r < 8; r++) {
                acc[r][0] = fma2(ad[r], b.x, acc[r][0]);
                acc[r][1] = fma2(ad[r], b.y, acc[r][1]);
            }
        }
        __syncthreads();
    }

    // combine row denominators (4 partials per row)
    atomicAdd(&denomS[bm], dsum);
    __syncthreads();

#pragma unroll
    for (int r = 0; r < 8; r++) {
        unsigned long long iv = dup2(1.0f / denomS[m0 + r]);
        ulonglong2 o;
        o.x = fma2(acc[r][0], iv, 0ULL);
        o.y = fma2(acc[r][1], iv, 0ULL);
        *(ulonglong2*)&out[(size_t)(i0 + m0 + r) * FOUT + c0 + n0] = o;
    }
}

// ============ launch =========================================================
extern "C" void kernel_launch(void* const* d_in, const int* in_sizes, int n_in,
                              void* d_out, int out_size) {
    const float* x   = (const float*)d_in[0];
    const int*   adj = (const int*)d_in[1];
    const float* W   = (const float*)d_in[2];
    const float* a   = (const float*)d_in[3];
    float* out = (float*)d_out;
    (void)in_sizes; (void)n_in; (void)out_size;

    dim3 g1(FOUT / 64, NV / 128);
    k_gemm_xw<<<g1, 256>>>(x, W);
    k_scores<<<NV / 8, 256>>>(a);
    dim3 g3(FOUT / 128, NV / 64);
    k_attn<<<g3, 256>>>(adj, out);
}

// round 16
// speedup vs baseline: 2.1895x; 2.1895x over previous
#include <cuda_runtime.h>
#include <cuda_bf16.h>
#include <math.h>
#include <stdint.h>

#define NV   8192
#define FIN  512
#define FOUT 256

// ---------------- scratch (device globals; allocation is forbidden) ----------
__device__ float  g_h[NV * FOUT];                        // h = x @ W (8 MB)
__device__ float4 g_sp[NV];                              // {s, e^s, e^{0.2s}, 0}
__device__ float4 g_dp[NV];                              // {d, e^d, e^{0.2d}, 0}
__device__ __align__(16) unsigned short g_hh[NV * FOUT]; // h hi bf16, [node][feat]
__device__ __align__(16) unsigned short g_hl[NV * FOUT]; // h lo bf16, [node][feat]

// ---------------- f32x2 helpers (kernel 1) -----------------------------------
__device__ __forceinline__ unsigned long long dup2(float v) {
    unsigned long long r;
    asm("mov.b64 %0, {%1, %1};" : "=l"(r) : "f"(v));
    return r;
}
__device__ __forceinline__ unsigned long long fma2(unsigned long long a,
                                                   unsigned long long b,
                                                   unsigned long long c) {
    unsigned long long d;
    asm("fma.rn.f32x2 %0, %1, %2, %3;" : "=l"(d) : "l"(a), "l"(b), "l"(c));
    return d;
}

// ---------------- bf16 split helpers -----------------------------------------
__device__ __forceinline__ unsigned pack_hi(float v0, float v1) {
    unsigned h;  // h.lo = bf16(v0), h.hi = bf16(v1)
    asm("cvt.rn.bf16x2.f32 %0, %1, %2;" : "=r"(h) : "f"(v1), "f"(v0));
    return h;
}
__device__ __forceinline__ unsigned pack_lo(float v0, float v1, unsigned h) {
    float l0 = v0 - __uint_as_float(h << 16);
    float l1 = v1 - __uint_as_float(h & 0xFFFF0000u);
    unsigned l;
    asm("cvt.rn.bf16x2.f32 %0, %1, %2;" : "=r"(l) : "f"(l1), "f"(l0));
    return l;
}

__device__ __forceinline__ uint32_t s2u(const void* p) {
    uint32_t a;
    asm("{ .reg .u64 t; cvta.to.shared.u64 t, %1; cvt.u32.u64 %0, t; }" : "=r"(a) : "l"(p));
    return a;
}

__device__ __forceinline__ void mma16816(float* c, const unsigned* a, unsigned b0, unsigned b1) {
    asm volatile(
        "mma.sync.aligned.m16n8k16.row.col.f32.bf16.bf16.f32 "
        "{%0,%1,%2,%3}, {%4,%5,%6,%7}, {%8,%9}, {%0,%1,%2,%3};"
        : "+f"(c[0]), "+f"(c[1]), "+f"(c[2]), "+f"(c[3])
        : "r"(a[0]), "r"(a[1]), "r"(a[2]), "r"(a[3]), "r"(b0), "r"(b1));
}
__device__ __forceinline__ void ldsm4t(unsigned* r, uint32_t addr) {
    asm volatile("ldmatrix.sync.aligned.m8n8.x4.trans.shared.b16 {%0,%1,%2,%3}, [%4];"
                 : "=r"(r[0]), "=r"(r[1]), "=r"(r[2]), "=r"(r[3]) : "r"(addr));
}

// ============ kernel 1: h = x @ W  (8192x512 @ 512x256), FFMA2 ===============
__global__ __launch_bounds__(256, 2) void k_gemm_xw(const float* __restrict__ x,
                                                    const float* __restrict__ W) {
    __shared__ float As[32][128];
    __shared__ float Ws[32][64];
    const int tid = threadIdx.x;
    const int i0 = blockIdx.y * 128, c0 = blockIdx.x * 64;
    const int bm = tid >> 1, kg = tid & 1;
    const int ty = tid >> 4, tx = tid & 15;
    const int m0 = ty * 8, n0 = tx * 4;

    unsigned long long acc[8][2];
#pragma unroll
    for (int r = 0; r < 8; r++) { acc[r][0] = 0ULL; acc[r][1] = 0ULL; }

    const float* xrow = x + (size_t)(i0 + bm) * FIN + kg * 16;

    for (int t = 0; t < FIN / 32; t++) {
        const int k0 = t * 32;
#pragma unroll
        for (int e = 0; e < 4; e++) {
            float4 v = *(const float4*)(xrow + k0 + e * 4);
            As[kg * 16 + e * 4 + 0][bm] = v.x;
            As[kg * 16 + e * 4 + 1][bm] = v.y;
            As[kg * 16 + e * 4 + 2][bm] = v.z;
            As[kg * 16 + e * 4 + 3][bm] = v.w;
        }
#pragma unroll
        for (int q = 0; q < 2; q++) {
            int idx = tid + q * 256;
            int r = idx >> 4, c4 = (idx & 15) * 4;
            *(float4*)&Ws[r][c4] = *(const float4*)(W + (size_t)(k0 + r) * FOUT + c0 + c4);
        }
        __syncthreads();
#pragma unroll
        for (int kk = 0; kk < 32; kk++) {
            float4 a0 = *(const float4*)&As[kk][m0];
            float4 a1 = *(const float4*)&As[kk][m0 + 4];
            ulonglong2 b = *(const ulonglong2*)&Ws[kk][n0];
            unsigned long long ad[8] = {dup2(a0.x), dup2(a0.y), dup2(a0.z), dup2(a0.w),
                                        dup2(a1.x), dup2(a1.y), dup2(a1.z), dup2(a1.w)};
#pragma unroll
            for (int r = 0; r < 8; r++) {
                acc[r][0] = fma2(ad[r], b.x, acc[r][0]);
                acc[r][1] = fma2(ad[r], b.y, acc[r][1]);
            }
        }
        __syncthreads();
    }
#pragma unroll
    for (int r = 0; r < 8; r++) {
        ulonglong2 o; o.x = acc[r][0]; o.y = acc[r][1];
        *(ulonglong2*)&g_h[(size_t)(i0 + m0 + r) * FOUT + c0 + n0] = o;
    }
}

// ============ kernel 2: per-node scores + exponentials =======================
__global__ void k_scores(const float* __restrict__ a) {
    const int node = blockIdx.x * 8 + (threadIdx.x >> 5);
    const int l = threadIdx.x & 31;
    const float* hr = g_h + (size_t)node * FOUT + l * 8;
    float4 h0 = *(const float4*)hr;
    float4 h1 = *(const float4*)(hr + 4);
    const float* aL = a + l * 8;
    const float* aR = a + FOUT + l * 8;
    float4 l0 = *(const float4*)aL, l1 = *(const float4*)(aL + 4);
    float4 r0 = *(const float4*)aR, r1 = *(const float4*)(aR + 4);
    float s = h0.x * l0.x + h0.y * l0.y + h0.z * l0.z + h0.w * l0.w
            + h1.x * l1.x + h1.y * l1.y + h1.z * l1.z + h1.w * l1.w;
    float d = h0.x * r0.x + h0.y * r0.y + h0.z * r0.z + h0.w * r0.w
            + h1.x * r1.x + h1.y * r1.y + h1.z * r1.z + h1.w * r1.w;
#pragma unroll
    for (int off = 16; off; off >>= 1) {
        s += __shfl_xor_sync(0xFFFFFFFFu, s, off);
        d += __shfl_xor_sync(0xFFFFFFFFu, d, off);
    }
    if (l == 0) {
        g_sp[node] = make_float4(s, expf(s), expf(0.2f * s), 0.f);
        g_dp[node] = make_float4(d, expf(d), expf(0.2f * d), 0.f);
    }
}

// ============ kernel 3: elementwise bf16 hi/lo split of h ====================
__global__ __launch_bounds__(256) void k_split() {
    const int base = (blockIdx.x * 256 + threadIdx.x) * 8;
    float4 v0 = *(const float4*)&g_h[base];
    float4 v1 = *(const float4*)&g_h[base + 4];
    unsigned h0 = pack_hi(v0.x, v0.y), h1 = pack_hi(v0.z, v0.w);
    unsigned h2 = pack_hi(v1.x, v1.y), h3 = pack_hi(v1.z, v1.w);
    unsigned q0 = pack_lo(v0.x, v0.y, h0), q1 = pack_lo(v0.z, v0.w, h1);
    unsigned q2 = pack_lo(v1.x, v1.y, h2), q3 = pack_lo(v1.z, v1.w, h3);
    *(uint4*)&g_hh[base] = make_uint4(h0, h1, h2, h3);
    *(uint4*)&g_hl[base] = make_uint4(q0, q1, q2, q3);
}

// ============ kernel 4: HMMA fused masked-softmax attention GEMM =============
// out = diag(1/denom) * P @ h; P built in registers directly as A-fragments.
// CTA 128(m) x 128(n), K chunks of 64; warp = m16 x n128; split-bf16 3-mma.
__global__ __launch_bounds__(256, 1) void k_attn_mma(const int* __restrict__ adj,
                                                     float* __restrict__ out) {
    __shared__ __align__(16) unsigned short Bh[64 * 128];
    __shared__ __align__(16) unsigned short Bl[64 * 128];
    __shared__ float denomS[128];

    const int tid = threadIdx.x;
    const int w = tid >> 5, lane = tid & 31;
    const int c0 = blockIdx.x * 128;
    const int i0 = blockIdx.y * 128;

    const uint32_t sbh = s2u(Bh), sbl = s2u(Bl);

    // fragment row/col mapping
    const int rgrp = lane >> 2;            // 0..7
    const int R0 = w * 16 + rgrp, R1 = R0 + 8;
    const int kb0 = 2 * (lane & 3);

    const int* aR0 = adj + (size_t)(i0 + R0) * NV;
    const int* aR1 = adj + (size_t)(i0 + R1) * NV;
    const float4 s0 = g_sp[i0 + R0];
    const float4 s1 = g_sp[i0 + R1];

    // B staging mapping: idx -> (k row, 16B chunk)
    // ldmatrix lane address precompute (per ks added later)
    const int g = lane >> 3;                       // matrix id 0..3
    const int lrow_base = (lane & 7) + ((g & 1) << 3);   // + ks*16
    const int lcol16 = ((g >> 1) << 3) * 2;              // byte offset of n-subtile

    float c[16][4];
#pragma unroll
    for (int nt = 0; nt < 16; nt++)
#pragma unroll
        for (int e = 0; e < 4; e++) c[nt][e] = 0.f;

    float dsum0 = 0.f, dsum1 = 0.f;

    // prefetch chunk 0 of B
    uint4 ph[4], pl[4];
#pragma unroll
    for (int q = 0; q < 4; q++) {
        int idx = tid + q * 256;
        int k = idx >> 4, nc = idx & 15;
        size_t src = (size_t)k * FOUT + c0 + nc * 8;
        ph[q] = *(const uint4*)&g_hh[src];
        pl[q] = *(const uint4*)&g_hl[src];
    }

    for (int t = 0; t < NV / 64; ++t) {
        const int k0 = t * 64;
        __syncthreads();
        // store staged B
#pragma unroll
        for (int q = 0; q < 4; q++) {
            int idx = tid + q * 256;
            int k = idx >> 4, nc = idx & 15;
            int off = k * 128 + (((nc * 16) ^ ((k & 7) << 4)) >> 1);  // in ushort units
            *(uint4*)&Bh[off] = ph[q];
            *(uint4*)&Bl[off] = pl[q];
        }
        __syncthreads();
        // prefetch next chunk
        if (t + 1 < NV / 64) {
#pragma unroll
            for (int q = 0; q < 4; q++) {
                int idx = tid + q * 256;
                int k = idx >> 4, nc = idx & 15;
                size_t src = (size_t)(k0 + 64 + k) * FOUT + c0 + nc * 8;
                ph[q] = *(const uint4*)&g_hh[src];
                pl[q] = *(const uint4*)&g_hl[src];
            }
        }

        // ---- build A fragments for this chunk (registers only) ----
        unsigned ah[4][4], al[4][4];
#pragma unroll
        for (int ks = 0; ks < 4; ++ks) {
            const int kb = ks * 16 + kb0;
            int2 m00 = *(const int2*)(aR0 + k0 + kb);
            int2 m01 = *(const int2*)(aR0 + k0 + kb + 8);
            int2 m10 = *(const int2*)(aR1 + k0 + kb);
            int2 m11 = *(const int2*)(aR1 + k0 + kb + 8);
            float4 dA = g_dp[k0 + kb],     dB = g_dp[k0 + kb + 1];
            float4 dC = g_dp[k0 + kb + 8], dD = g_dp[k0 + kb + 9];

            float zA0 = s0.x + dA.x, zB0 = s0.x + dB.x, zC0 = s0.x + dC.x, zD0 = s0.x + dD.x;
            float v00 = (zA0 > 0.f) ? s0.y * dA.y : s0.z * dA.z;
            float v01 = (zB0 > 0.f) ? s0.y * dB.y : s0.z * dB.z;
            float v02 = (zC0 > 0.f) ? s0.y * dC.y : s0.z * dC.z;
            float v03 = (zD0 > 0.f) ? s0.y * dD.y : s0.z * dD.z;
            v00 = (m00.x > 0) ? v00 : 0.f;  v01 = (m00.y > 0) ? v01 : 0.f;
            v02 = (m01.x > 0) ? v02 : 0.f;  v03 = (m01.y > 0) ? v03 : 0.f;

            float zA1 = s1.x + dA.x, zB1 = s1.x + dB.x, zC1 = s1.x + dC.x, zD1 = s1.x + dD.x;
            float v10 = (zA1 > 0.f) ? s1.y * dA.y : s1.z * dA.z;
            float v11 = (zB1 > 0.f) ? s1.y * dB.y : s1.z * dB.z;
            float v12 = (zC1 > 0.f) ? s1.y * dC.y : s1.z * dC.z;
            float v13 = (zD1 > 0.f) ? s1.y * dD.y : s1.z * dD.z;
            v10 = (m10.x > 0) ? v10 : 0.f;  v11 = (m10.y > 0) ? v11 : 0.f;
            v12 = (m11.x > 0) ? v12 : 0.f;  v13 = (m11.y > 0) ? v13 : 0.f;

            dsum0 += (v00 + v01) + (v02 + v03);
            dsum1 += (v10 + v11) + (v12 + v13);

            ah[ks][0] = pack_hi(v00, v01);  al[ks][0] = pack_lo(v00, v01, ah[ks][0]);
            ah[ks][1] = pack_hi(v10, v11);  al[ks][1] = pack_lo(v10, v11, ah[ks][1]);
            ah[ks][2] = pack_hi(v02, v03);  al[ks][2] = pack_lo(v02, v03, ah[ks][2]);
            ah[ks][3] = pack_hi(v12, v13);  al[ks][3] = pack_lo(v12, v13, ah[ks][3]);
        }

        // ---- ldsm B + 3-way split MMAs ----
#pragma unroll
        for (int ks = 0; ks < 4; ++ks) {
            const int lrow = ks * 16 + lrow_base;
            const int rsw = ((lrow & 7) << 4);
#pragma unroll
            for (int np = 0; np < 8; ++np) {
                const int boff = lrow * 256 + ((np * 32 + lcol16) ^ rsw);
                unsigned bh[4], bl[4];
                ldsm4t(bh, sbh + boff);
                ldsm4t(bl, sbl + boff);
                mma16816(c[2 * np],     ah[ks], bh[0], bh[1]);
                mma16816(c[2 * np],     ah[ks], bl[0], bl[1]);
                mma16816(c[2 * np],     al[ks], bh[0], bh[1]);
                mma16816(c[2 * np + 1], ah[ks], bh[2], bh[3]);
                mma16816(c[2 * np + 1], ah[ks], bl[2], bl[3]);
                mma16816(c[2 * np + 1], al[ks], bh[2], bh[3]);
            }
        }
    }

    // ---- row denominators: reduce across the 4 lanes sharing each row ----
    dsum0 += __shfl_xor_sync(0xFFFFFFFFu, dsum0, 1);
    dsum0 += __shfl_xor_sync(0xFFFFFFFFu, dsum0, 2);
    dsum1 += __shfl_xor_sync(0xFFFFFFFFu, dsum1, 1);
    dsum1 += __shfl_xor_sync(0xFFFFFFFFu, dsum1, 2);
    if ((lane & 3) == 0) { denomS[R0] = dsum0; denomS[R1] = dsum1; }
    __syncthreads();
    const float inv0 = 1.0f / denomS[R0];
    const float inv1 = 1.0f / denomS[R1];

    // ---- epilogue ----
    float* o0 = out + (size_t)(i0 + R0) * FOUT + c0 + 2 * (lane & 3);
    float* o1 = out + (size_t)(i0 + R1) * FOUT + c0 + 2 * (lane & 3);
#pragma unroll
    for (int nt = 0; nt < 16; nt++) {
        *(float2*)(o0 + nt * 8) = make_float2(c[nt][0] * inv0, c[nt][1] * inv0);
        *(float2*)(o1 + nt * 8) = make_float2(c[nt][2] * inv1, c[nt][3] * inv1);
    }
}

// ============ launch =========================================================
extern "C" void kernel_launch(void* const* d_in, const int* in_sizes, int n_in,
                              void* d_out, int out_size) {
    const float* x   = (const float*)d_in[0];
    const int*   adj = (const int*)d_in[1];
    const float* W   = (const float*)d_in[2];
    const float* a   = (const float*)d_in[3];
    float* out = (float*)d_out;
    (void)in_sizes; (void)n_in; (void)out_size;

    dim3 g1(FOUT / 64, NV / 128);
    k_gemm_xw<<<g1, 256>>>(x, W);
    k_scores<<<NV / 8, 256>>>(a);
    k_split<<<NV * FOUT / (256 * 8), 256>>>();
    dim3 g3(2, NV / 128);
    k_attn_mma<<<g3, 256>>>(adj, out);
}